// round 1
// baseline (speedup 1.0000x reference)
#include <cuda_runtime.h>
#include <cstdint>

// Problem constants
#define NB     64
#define CIN    64
#define COUT   128
#define NT     300
#define NV     25
#define TV     7500          // NT*NV
#define TT     5             // t per tile
#define NTILE  125           // cols per tile (TT*NV)
#define NTILES 60            // NT/TT
#define NPAD   128           // padded cols in scratch
#define NCNT   480000        // NB*NT*NV per-channel count

// Scratch: y in padded layout [b][o][tile][128]
__device__ float g_ys[(size_t)NB * COUT * NTILES * NPAD];
__device__ float g_sum[COUT];
__device__ float g_sq[COUT];
__device__ float g_scale[COUT];
__device__ float g_shift[COUT];

typedef unsigned long long ull;

__device__ __forceinline__ ull dup2(float x) {
    ull r; asm("mov.b64 %0, {%1, %1};" : "=l"(r) : "f"(x)); return r;
}
__device__ __forceinline__ void fma2(ull& d, ull a, ull b) {
    asm("fma.rn.f32x2 %0, %1, %2, %3;" : "=l"(d) : "l"(a), "l"(b), "l"(d));
}
__device__ __forceinline__ float2 unpk(ull v) {
    float2 f; asm("mov.b64 {%0, %1}, %2;" : "=f"(f.x), "=f"(f.y) : "l"(v)); return f;
}

// Shared memory layout (floats):
//   s_x   [64][132]  (x tile -> becomes xg in place; stride 132 keeps 16B alignment)
//   s_wt  [64][130]  (W transposed: s_wt[c][o] = W[o][c]; stride 130 kills STS conflicts)
//   s_adj [25][26]   (col 25 zero-padded for f32x2 pairs)
//   s_bias[128]
#define SX_OFF   0
#define SX_STR   132
#define SWT_OFF  (64*132)          // 8448
#define SWT_STR  130
#define SADJ_OFF (SWT_OFF + 64*130)   // 16768
#define SBIAS_OFF (SADJ_OFF + 650)    // 17418
#define SMEM_FLOATS (SBIAS_OFF + 128) // 17546
#define SMEM_BYTES (SMEM_FLOATS * 4)  // 70184

__global__ void k0_zero() {
    int t = threadIdx.x;
    if (t < COUT) g_sum[t] = 0.f;
    else if (t < 2*COUT) g_sq[t - COUT] = 0.f;
}

__global__ void __launch_bounds__(256, 2)
k1_fused(const float* __restrict__ x, const float* __restrict__ adj,
         const float* __restrict__ W, const float* __restrict__ bias)
{
    extern __shared__ float sm[];
    float* s_x    = sm + SX_OFF;
    float* s_wt   = sm + SWT_OFF;
    float* s_adj  = sm + SADJ_OFF;
    float* s_bias = sm + SBIAS_OFF;

    const int tid = threadIdx.x;
    const int blk = blockIdx.x;
    const int b   = blk / NTILES;
    const int tt  = blk - b * NTILES;

    // ---- cooperative loads ----
    const float* xb = x + (size_t)b * CIN * TV + (size_t)tt * NTILE;
    for (int idx = tid; idx < CIN * NTILE; idx += 256) {
        int c = idx / NTILE, j = idx - c * NTILE;
        s_x[c * SX_STR + j] = xb[(size_t)c * TV + j];
    }
    if (tid < 192) {  // zero pad cols 125..127
        int c = tid / 3, k = tid - c * 3;
        s_x[c * SX_STR + NTILE + k] = 0.f;
    }
    for (int idx = tid; idx < COUT * CIN; idx += 256) {
        int o = idx >> 6, c = idx & 63;          // coalesced gmem read
        s_wt[c * SWT_STR + o] = W[idx];          // 2-way STS conflict only
    }
    for (int idx = tid; idx < 650; idx += 256) {
        int v = idx / 26, w = idx - v * 26;
        s_adj[idx] = (w < NV) ? adj[v * NV + w] : 0.f;
    }
    if (tid < COUT) s_bias[tid] = bias[tid];
    __syncthreads();

    // ---- adjacency transform, in place: xg[c][25tl+w] = sum_v x[c][25tl+v]*adj[v][w] ----
    for (int task = tid; task < CIN * TT; task += 256) {
        int c = task / TT, tl = task - c * TT;
        float* xr_ptr = s_x + c * SX_STR + tl * NV;
        float xr[NV];
        #pragma unroll
        for (int v = 0; v < NV; ++v) xr[v] = xr_ptr[v];
        ull acc[13];
        #pragma unroll
        for (int p = 0; p < 13; ++p) acc[p] = 0ull;   // bits 0 == {0.f,0.f}
        #pragma unroll
        for (int v = 0; v < NV; ++v) {
            ull xv = dup2(xr[v]);
            const ull* arow = (const ull*)(s_adj + v * 26);
            #pragma unroll
            for (int p = 0; p < 13; ++p) fma2(acc[p], xv, arow[p]);
        }
        #pragma unroll
        for (int p = 0; p < 12; ++p) {
            float2 f = unpk(acc[p]);
            xr_ptr[2 * p] = f.x; xr_ptr[2 * p + 1] = f.y;
        }
        { float2 f = unpk(acc[12]); xr_ptr[24] = f.x; }  // w=25 is pad, dropped
    }
    __syncthreads();

    // ---- main GEMM: y[128][128(125)] = Wt^T @ xg ; thread tile 8M x 8N ----
    const int tx = tid & 15;   // N
    const int ty = tid >> 4;   // M
    ull acc[8][4];
    #pragma unroll
    for (int i = 0; i < 8; ++i)
        #pragma unroll
        for (int p = 0; p < 4; ++p) acc[i][p] = 0ull;

    #pragma unroll 4
    for (int c = 0; c < CIN; ++c) {
        const float* wr = s_wt + c * SWT_STR + ty * 8;
        float2 a0 = *(const float2*)(wr);
        float2 a1 = *(const float2*)(wr + 2);
        float2 a2 = *(const float2*)(wr + 4);
        float2 a3 = *(const float2*)(wr + 6);
        const float* xr = s_x + c * SX_STR + tx * 4;
        ulonglong2 b0 = *(const ulonglong2*)(xr);        // cols 4tx..4tx+3
        ulonglong2 b1 = *(const ulonglong2*)(xr + 64);   // cols 64+4tx..+3
        ull ad;
        ad = dup2(a0.x); fma2(acc[0][0],ad,b0.x); fma2(acc[0][1],ad,b0.y); fma2(acc[0][2],ad,b1.x); fma2(acc[0][3],ad,b1.y);
        ad = dup2(a0.y); fma2(acc[1][0],ad,b0.x); fma2(acc[1][1],ad,b0.y); fma2(acc[1][2],ad,b1.x); fma2(acc[1][3],ad,b1.y);
        ad = dup2(a1.x); fma2(acc[2][0],ad,b0.x); fma2(acc[2][1],ad,b0.y); fma2(acc[2][2],ad,b1.x); fma2(acc[2][3],ad,b1.y);
        ad = dup2(a1.y); fma2(acc[3][0],ad,b0.x); fma2(acc[3][1],ad,b0.y); fma2(acc[3][2],ad,b1.x); fma2(acc[3][3],ad,b1.y);
        ad = dup2(a2.x); fma2(acc[4][0],ad,b0.x); fma2(acc[4][1],ad,b0.y); fma2(acc[4][2],ad,b1.x); fma2(acc[4][3],ad,b1.y);
        ad = dup2(a2.y); fma2(acc[5][0],ad,b0.x); fma2(acc[5][1],ad,b0.y); fma2(acc[5][2],ad,b1.x); fma2(acc[5][3],ad,b1.y);
        ad = dup2(a3.x); fma2(acc[6][0],ad,b0.x); fma2(acc[6][1],ad,b0.y); fma2(acc[6][2],ad,b1.x); fma2(acc[6][3],ad,b1.y);
        ad = dup2(a3.y); fma2(acc[7][0],ad,b0.x); fma2(acc[7][1],ad,b0.y); fma2(acc[7][2],ad,b1.x); fma2(acc[7][3],ad,b1.y);
    }

    // ---- epilogue: bias, store to padded scratch, per-channel sum/sumsq ----
    const size_t ybase = (size_t)(b * COUT) * (NTILES * NPAD) + (size_t)tt * NPAD;
    const int n0 = tx * 4;
    #pragma unroll
    for (int i = 0; i < 8; ++i) {
        int o = ty * 8 + i;
        float bb = s_bias[o];
        float2 p0 = unpk(acc[i][0]), p1 = unpk(acc[i][1]);
        float2 p2 = unpk(acc[i][2]), p3 = unpk(acc[i][3]);
        float y0 = p0.x + bb, y1 = p0.y + bb, y2 = p1.x + bb, y3 = p1.y + bb;
        float y4 = p2.x + bb, y5 = p2.y + bb, y6 = p3.x + bb, y7 = p3.y + bb;
        float* yp = g_ys + ybase + (size_t)o * (NTILES * NPAD);
        *(float4*)(yp + n0)      = make_float4(y0, y1, y2, y3);
        *(float4*)(yp + 64 + n0) = make_float4(y4, y5, y6, y7);  // pad cols never read
        float rs = y0 + y1 + y2 + y3;
        float rq = y0*y0 + y1*y1 + y2*y2 + y3*y3;
        if (tx < 15) { rs += y4 + y5 + y6 + y7; rq += y4*y4 + y5*y5 + y6*y6 + y7*y7; }
        else         { rs += y4;                rq += y4*y4; }   // cols 125..127 invalid
        #pragma unroll
        for (int m = 1; m < 16; m <<= 1) {
            rs += __shfl_xor_sync(0xffffffffu, rs, m);
            rq += __shfl_xor_sync(0xffffffffu, rq, m);
        }
        if (tx == 0) { atomicAdd(&g_sum[o], rs); atomicAdd(&g_sq[o], rq); }
    }
}

__global__ void k2_finalize(const float* __restrict__ gamma, const float* __restrict__ beta) {
    int i = threadIdx.x;  // 128 threads
    float mean = g_sum[i] * (1.0f / NCNT);
    float var  = g_sq[i]  * (1.0f / NCNT) - mean * mean;
    float sc   = gamma[i] * rsqrtf(var + 1e-5f);
    g_scale[i] = sc;
    g_shift[i] = beta[i] - mean * sc;
}

__global__ void k3_norm(float* __restrict__ out) {
    unsigned int idx = blockIdx.x * 256u + threadIdx.x;
    unsigned int e = idx * 4u;
    if (e >= 61440000u) return;
    unsigned int row = e / TV;          // (b*128+o)
    int o = row & 127;
    unsigned int g = e - row * TV;
    const float* yrow = g_ys + (size_t)row * (NTILES * NPAD);
    float sc = g_scale[o], sh = g_shift[o];
    float4 r;
    {
        unsigned int gg = g;     unsigned int t0 = gg / NTILE; r.x = fmaxf(fmaf(yrow[t0 * NPAD + (gg - t0 * NTILE)], sc, sh), 0.f);
    }
    {
        unsigned int gg = g + 1; unsigned int t0 = gg / NTILE; r.y = fmaxf(fmaf(yrow[t0 * NPAD + (gg - t0 * NTILE)], sc, sh), 0.f);
    }
    {
        unsigned int gg = g + 2; unsigned int t0 = gg / NTILE; r.z = fmaxf(fmaf(yrow[t0 * NPAD + (gg - t0 * NTILE)], sc, sh), 0.f);
    }
    {
        unsigned int gg = g + 3; unsigned int t0 = gg / NTILE; r.w = fmaxf(fmaf(yrow[t0 * NPAD + (gg - t0 * NTILE)], sc, sh), 0.f);
    }
    *(float4*)(out + e) = r;
}

extern "C" void kernel_launch(void* const* d_in, const int* in_sizes, int n_in,
                              void* d_out, int out_size)
{
    (void)in_sizes; (void)n_in; (void)out_size;
    const float* x     = (const float*)d_in[0];
    const float* adj   = (const float*)d_in[1];
    const float* W     = (const float*)d_in[2];
    const float* bias  = (const float*)d_in[3];
    const float* gamma = (const float*)d_in[4];
    const float* beta  = (const float*)d_in[5];
    float* out = (float*)d_out;

    cudaFuncSetAttribute(k1_fused, cudaFuncAttributeMaxDynamicSharedMemorySize, SMEM_BYTES);

    k0_zero<<<1, 256>>>();
    k1_fused<<<NB * NTILES, 256, SMEM_BYTES>>>(x, adj, W, bias);
    k2_finalize<<<1, 128>>>(gamma, beta);
    k3_norm<<<60000, 256>>>(out);
}

// round 3
// speedup vs baseline: 1.2550x; 1.2550x over previous
#include <cuda_runtime.h>
#include <cuda_bf16.h>
#include <cstdint>

// Problem constants
#define NB     64
#define CIN    64
#define COUT   128
#define NT     300
#define NV     25
#define TV     7500          // NT*NV
#define TT     5             // t per tile
#define NTILE  125           // cols per tile
#define NTILES 60            // NT/TT
#define NCNT   480000        // NB*NT*NV

// Scratch: y in EXACT output layout [b][o][7500]
__device__ float g_ys[(size_t)NB * COUT * TV];
__device__ float g_sum[COUT];
__device__ float g_sq[COUT];
__device__ float g_scale[COUT];
__device__ float g_shift[COUT];

typedef unsigned long long ull;

// ---------------- SMEM layout (bytes) ----------------
// A tiles: [o=128][c] bf16, row stride 72 halves (144B) -> conflict-free ldmatrix
// B tiles: [c=64][j] bf16, row stride 136 halves (272B) -> conflict-free ldmatrix.trans
#define A_STR     72
#define B_STR     136
#define OFF_WHI   0                         // 128*72*2 = 18432
#define OFF_WLO   18432                     // 18432
#define OFF_BHI   36864                     // 64*136*2 = 17408
#define OFF_BLO   54272                     // 17408
#define OFF_X     71680                     // 64*132*4 = 33792 (x tile fp32; reused as staging)
#define SX_STR    132
#define OFF_ADJ   105472                    // 650*4 = 2600
#define OFF_BIAS  108080                    // 512
#define SMEM_BYTES 108592

__device__ __forceinline__ uint32_t smem_u32(const void* p) {
    uint32_t a;
    asm("{ .reg .u64 t; cvta.to.shared.u64 t, %1; cvt.u32.u64 %0, t; }" : "=r"(a) : "l"(p));
    return a;
}
__device__ __forceinline__ ull dup2(float x) {
    ull r; asm("mov.b64 %0, {%1, %1};" : "=l"(r) : "f"(x)); return r;
}
__device__ __forceinline__ void fma2(ull& d, ull a, ull b) {
    asm("fma.rn.f32x2 %0, %1, %2, %3;" : "=l"(d) : "l"(a), "l"(b), "l"(d));
}
__device__ __forceinline__ float2 unpk(ull v) {
    float2 f; asm("mov.b64 {%0, %1}, %2;" : "=f"(f.x), "=f"(f.y) : "l"(v)); return f;
}
__device__ __forceinline__ void ldm_x4(uint32_t* r, uint32_t addr) {
    asm volatile("ldmatrix.sync.aligned.m8n8.x4.shared.b16 {%0,%1,%2,%3}, [%4];"
        : "=r"(r[0]), "=r"(r[1]), "=r"(r[2]), "=r"(r[3]) : "r"(addr));
}
__device__ __forceinline__ void ldm_x4_t(uint32_t* r, uint32_t addr) {
    asm volatile("ldmatrix.sync.aligned.m8n8.x4.trans.shared.b16 {%0,%1,%2,%3}, [%4];"
        : "=r"(r[0]), "=r"(r[1]), "=r"(r[2]), "=r"(r[3]) : "r"(addr));
}
__device__ __forceinline__ void mma16816(float* d, const uint32_t* a, uint32_t b0, uint32_t b1) {
    asm volatile("mma.sync.aligned.m16n8k16.row.col.f32.bf16.bf16.f32 "
        "{%0,%1,%2,%3}, {%4,%5,%6,%7}, {%8,%9}, {%0,%1,%2,%3};"
        : "+f"(d[0]), "+f"(d[1]), "+f"(d[2]), "+f"(d[3])
        : "r"(a[0]), "r"(a[1]), "r"(a[2]), "r"(a[3]), "r"(b0), "r"(b1));
}

__global__ void k0_zero() {
    int t = threadIdx.x;
    if (t < COUT) g_sum[t] = 0.f;
    else if (t < 2 * COUT) g_sq[t - COUT] = 0.f;
}

__global__ void __launch_bounds__(256, 2)
k1_fused(const float* __restrict__ x, const float* __restrict__ adj,
         const float* __restrict__ W, const float* __restrict__ bias)
{
    extern __shared__ char sm[];
    const uint32_t smb = smem_u32(sm);
    float* s_x    = (float*)(sm + OFF_X);
    float* s_adj  = (float*)(sm + OFF_ADJ);
    float* s_bias = (float*)(sm + OFF_BIAS);
    __nv_bfloat16* whi = (__nv_bfloat16*)(sm + OFF_WHI);
    __nv_bfloat16* wlo = (__nv_bfloat16*)(sm + OFF_WLO);
    __nv_bfloat16* bhi = (__nv_bfloat16*)(sm + OFF_BHI);
    __nv_bfloat16* blo = (__nv_bfloat16*)(sm + OFF_BLO);

    const int tid = threadIdx.x;
    const int wid = tid >> 5;
    const int lid = tid & 31;
    const int blk = blockIdx.x;
    const int b   = blk / NTILES;
    const int tt  = blk - b * NTILES;

    // ---- cooperative loads + zero B tiles (pad cols must be 0) ----
    const float* xb = x + (size_t)b * CIN * TV + (size_t)tt * NTILE;
    for (int idx = tid; idx < CIN * NTILE; idx += 256) {
        int c = idx / NTILE, j = idx - c * NTILE;
        s_x[c * SX_STR + j] = xb[(size_t)c * TV + j];
    }
    {   // zero bhi+blo (contiguous 34816B)
        uint4* z = (uint4*)(sm + OFF_BHI);
        for (int i = tid; i < (2 * 64 * B_STR * 2) / 16; i += 256)
            z[i] = make_uint4(0u, 0u, 0u, 0u);
    }
    for (int idx = tid; idx < 650; idx += 256) {
        int v = idx / 26, w = idx - v * 26;
        s_adj[idx] = (w < NV) ? adj[v * NV + w] : 0.f;
    }
    if (tid < COUT) s_bias[tid] = bias[tid];
    // W -> bf16 hi/lo A tiles [o][c]
    for (int idx = tid; idx < COUT * CIN; idx += 256) {
        int o = idx >> 6, c = idx & 63;
        float v = W[idx];
        __nv_bfloat16 h = __float2bfloat16_rn(v);
        __nv_bfloat16 l = __float2bfloat16_rn(v - __bfloat162float(h));
        whi[o * A_STR + c] = h;
        wlo[o * A_STR + c] = l;
    }
    __syncthreads();

    // ---- adjacency (fp32/f32x2), writing bf16 hi/lo B tiles directly ----
    // xg[c][25tl+w] = sum_v x[c][25tl+v]*adj[v][w]
    for (int task = tid; task < CIN * TT; task += 256) {
        int c = task / TT, tl = task - c * TT;
        const float* xr_ptr = s_x + c * SX_STR + tl * NV;
        float xr[NV];
        #pragma unroll
        for (int v = 0; v < NV; ++v) xr[v] = xr_ptr[v];
        ull acc[13];
        #pragma unroll
        for (int p = 0; p < 13; ++p) acc[p] = 0ull;
        #pragma unroll
        for (int v = 0; v < NV; ++v) {
            ull xv = dup2(xr[v]);
            const ull* arow = (const ull*)(s_adj + v * 26);
            #pragma unroll
            for (int p = 0; p < 13; ++p) fma2(acc[p], xv, arow[p]);
        }
        __nv_bfloat16* bh = bhi + c * B_STR + tl * NV;
        __nv_bfloat16* bl = blo + c * B_STR + tl * NV;
        #pragma unroll
        for (int p = 0; p < 13; ++p) {
            float2 f = unpk(acc[p]);
            int w = 2 * p;
            {
                __nv_bfloat16 h = __float2bfloat16_rn(f.x);
                bh[w] = h; bl[w] = __float2bfloat16_rn(f.x - __bfloat162float(h));
            }
            if (w + 1 < NV) {
                __nv_bfloat16 h = __float2bfloat16_rn(f.y);
                bh[w + 1] = h; bl[w + 1] = __float2bfloat16_rn(f.y - __bfloat162float(h));
            }
        }
    }
    __syncthreads();

    // ---- HMMA GEMM: D[128o][128j] = Wt @ Xg^T, 3-term bf16 split ----
    const int warpM = wid >> 1;          // 0..3 -> rows 32*warpM
    const int warpN = wid & 1;           // 0..1 -> cols 64*warpN
    const int mbase = warpM * 32;
    const int nbase = warpN * 64;
    const int lrow  = lid & 15;          // ldmatrix row lane
    const int lcol8 = (lid >> 4) * 8;    // ldmatrix col-block

    float acc[2][8][4];
    #pragma unroll
    for (int mt = 0; mt < 2; ++mt)
        #pragma unroll
        for (int nt = 0; nt < 8; ++nt)
            #pragma unroll
            for (int e = 0; e < 4; ++e) acc[mt][nt][e] = 0.f;

    #pragma unroll
    for (int ks = 0; ks < 4; ++ks) {
        uint32_t ahi[2][4], alo[2][4];
        #pragma unroll
        for (int mt = 0; mt < 2; ++mt) {
            uint32_t arow = mbase + mt * 16 + lrow;
            uint32_t acolb = ks * 16 + lcol8;
            ldm_x4(ahi[mt], smb + OFF_WHI + (arow * A_STR + acolb) * 2);
            ldm_x4(alo[mt], smb + OFF_WLO + (arow * A_STR + acolb) * 2);
        }
        #pragma unroll
        for (int nh = 0; nh < 2; ++nh) {
            uint32_t bhF[2][4], blF[2][4];
            #pragma unroll
            for (int nt2 = 0; nt2 < 2; ++nt2) {
                uint32_t brow = ks * 16 + lrow;
                uint32_t bcol = nbase + nh * 32 + nt2 * 16 + lcol8;
                ldm_x4_t(bhF[nt2], smb + OFF_BHI + (brow * B_STR + bcol) * 2);
                ldm_x4_t(blF[nt2], smb + OFF_BLO + (brow * B_STR + bcol) * 2);
            }
            #pragma unroll
            for (int mt = 0; mt < 2; ++mt)
                #pragma unroll
                for (int nt = 0; nt < 4; ++nt) {
                    float* d = acc[mt][nh * 4 + nt];
                    uint32_t b0h = bhF[nt >> 1][(nt & 1) * 2], b1h = bhF[nt >> 1][(nt & 1) * 2 + 1];
                    uint32_t b0l = blF[nt >> 1][(nt & 1) * 2], b1l = blF[nt >> 1][(nt & 1) * 2 + 1];
                    mma16816(d, ahi[mt], b0h, b1h);
                    mma16816(d, ahi[mt], b0l, b1l);
                    mma16816(d, alo[mt], b0h, b1h);
                }
        }
    }

    // ---- bias + per-channel stats (quad shuffles) ----
    const int qrow = lid >> 2;           // 0..7
    const int qcol = (lid & 3) * 2;      // 0,2,4,6
    float rsum[2][2] = {{0.f, 0.f}, {0.f, 0.f}};
    float rsq[2][2]  = {{0.f, 0.f}, {0.f, 0.f}};
    #pragma unroll
    for (int mt = 0; mt < 2; ++mt) {
        int r0 = mbase + mt * 16 + qrow;
        float b0 = s_bias[r0], b1 = s_bias[r0 + 8];
        #pragma unroll
        for (int nt = 0; nt < 8; ++nt) {
            int j0 = nbase + nt * 8 + qcol;
            float* d = acc[mt][nt];
            d[0] += b0; d[1] += b0; d[2] += b1; d[3] += b1;
            if (j0 < NTILE)     { rsum[mt][0] += d[0]; rsq[mt][0] += d[0] * d[0];
                                  rsum[mt][1] += d[2]; rsq[mt][1] += d[2] * d[2]; }
            if (j0 + 1 < NTILE) { rsum[mt][0] += d[1]; rsq[mt][0] += d[1] * d[1];
                                  rsum[mt][1] += d[3]; rsq[mt][1] += d[3] * d[3]; }
        }
    }
    #pragma unroll
    for (int mt = 0; mt < 2; ++mt)
        #pragma unroll
        for (int rr = 0; rr < 2; ++rr) {
            float s = rsum[mt][rr], q = rsq[mt][rr];
            s += __shfl_xor_sync(0xffffffffu, s, 1); q += __shfl_xor_sync(0xffffffffu, q, 1);
            s += __shfl_xor_sync(0xffffffffu, s, 2); q += __shfl_xor_sync(0xffffffffu, q, 2);
            if ((lid & 3) == 0) {
                int o = mbase + mt * 16 + qrow + rr * 8;
                atomicAdd(&g_sum[o], s);
                atomicAdd(&g_sq[o], q);
            }
        }

    // ---- staged coalesced store to scratch ----
    float* s_stage = s_x;   // 32 x 133 floats
    const size_t tile_base = (size_t)b * COUT * TV + (size_t)tt * NTILE;
    #pragma unroll
    for (int ch = 0; ch < 4; ++ch) {
        __syncthreads();
        if (warpN == (ch >> 1)) {
            int nt0 = (ch & 1) * 4;
            #pragma unroll
            for (int mt = 0; mt < 2; ++mt) {
                int r0 = mbase + mt * 16 + qrow;
                #pragma unroll
                for (int nt = 0; nt < 4; ++nt) {
                    float* d = acc[mt][nt0 + nt];
                    int jl = nt * 8 + qcol;      // 0..31 within chunk
                    s_stage[jl * 133 + r0]           = d[0];
                    s_stage[(jl + 1) * 133 + r0]     = d[1];
                    s_stage[jl * 133 + r0 + 8]       = d[2];
                    s_stage[(jl + 1) * 133 + r0 + 8] = d[3];
                }
            }
        }
        __syncthreads();
        int j = ch * 32 + lid;
        if (j < NTILE) {
            #pragma unroll
            for (int k = 0; k < 16; ++k) {
                int o = wid + k * 8;
                g_ys[tile_base + (size_t)o * TV + j] = s_stage[lid * 133 + o];
            }
        }
    }
}

__global__ void k2_finalize(const float* __restrict__ gamma, const float* __restrict__ beta) {
    int i = threadIdx.x;
    float mean = g_sum[i] * (1.0f / NCNT);
    float var  = g_sq[i]  * (1.0f / NCNT) - mean * mean;
    float sc   = gamma[i] * rsqrtf(var + 1e-5f);
    g_scale[i] = sc;
    g_shift[i] = beta[i] - mean * sc;
}

__global__ void k3_norm(float* __restrict__ out) {
    unsigned int idx = blockIdx.x * 256u + threadIdx.x;
    unsigned int e = idx * 4u;
    if (e >= 61440000u) return;
    unsigned int row = e / TV;
    int o = row & 127;
    float sc = g_scale[o], sh = g_shift[o];
    float4 y = *(const float4*)(g_ys + e);
    float4 r;
    r.x = fmaxf(fmaf(y.x, sc, sh), 0.f);
    r.y = fmaxf(fmaf(y.y, sc, sh), 0.f);
    r.z = fmaxf(fmaf(y.z, sc, sh), 0.f);
    r.w = fmaxf(fmaf(y.w, sc, sh), 0.f);
    *(float4*)(out + e) = r;
}

extern "C" void kernel_launch(void* const* d_in, const int* in_sizes, int n_in,
                              void* d_out, int out_size)
{
    (void)in_sizes; (void)n_in; (void)out_size;
    const float* x     = (const float*)d_in[0];
    const float* adj   = (const float*)d_in[1];
    const float* W     = (const float*)d_in[2];
    const float* bias  = (const float*)d_in[3];
    const float* gamma = (const float*)d_in[4];
    const float* beta  = (const float*)d_in[5];
    float* out = (float*)d_out;

    cudaFuncSetAttribute(k1_fused, cudaFuncAttributeMaxDynamicSharedMemorySize, SMEM_BYTES);

    k0_zero<<<1, 256>>>();
    k1_fused<<<NB * NTILES, 256, SMEM_BYTES>>>(x, adj, W, bias);
    k2_finalize<<<1, 128>>>(gamma, beta);
    k3_norm<<<60000, 256>>>(out);
}

// round 4
// speedup vs baseline: 1.4853x; 1.1835x over previous
#include <cuda_runtime.h>
#include <cuda_bf16.h>
#include <cuda_fp16.h>
#include <cstdint>

// Problem constants
#define NB     64
#define CIN    64
#define COUT   128
#define NT     300
#define NV     25
#define TV     7500          // NT*NV
#define TT     5             // t per tile
#define NTILE  125           // cols per tile
#define NTILES 60            // NT/TT
#define NCNT   480000        // NB*NT*NV

// Scratch: y as fp16, padded layout [b][o][tile][128]
__device__ __half g_ys[(size_t)NB * COUT * NTILES * 128];
__device__ float g_sum[COUT];
__device__ float g_sq[COUT];
__device__ float g_scale[COUT];
__device__ float g_shift[COUT];

typedef unsigned long long ull;

// ---------------- SMEM layout (bytes) ----------------
// A tiles: [o=128][c] bf16, row stride 72 halves -> conflict-free ldmatrix
// B tiles: [c=64][j] bf16, row stride 136 halves -> conflict-free ldmatrix.trans
// Staging (fp16 y, [o=128][j] stride 136) aliases BHI+BLO after MMA.
#define A_STR     72
#define B_STR     136
#define OFF_WHI   0                       // 128*72*2 = 18432
#define OFF_WLO   18432                   // 18432
#define OFF_BHI   36864                   // 64*136*2 = 17408
#define OFF_BLO   54272                   // 17408  (BHI+BLO = 34816 = staging 128*136*2)
#define OFF_ADJ   71680                   // 650*4 = 2600
#define OFF_SSUM  74280                   // 512
#define OFF_SSQ   74792                   // 512
#define OFF_BIAS  75304                   // 512
#define SMEM_BYTES 75816

__device__ __forceinline__ uint32_t smem_u32(const void* p) {
    uint32_t a;
    asm("{ .reg .u64 t; cvta.to.shared.u64 t, %1; cvt.u32.u64 %0, t; }" : "=r"(a) : "l"(p));
    return a;
}
__device__ __forceinline__ ull dup2(float x) {
    ull r; asm("mov.b64 %0, {%1, %1};" : "=l"(r) : "f"(x)); return r;
}
__device__ __forceinline__ void fma2(ull& d, ull a, ull b) {
    asm("fma.rn.f32x2 %0, %1, %2, %3;" : "=l"(d) : "l"(a), "l"(b), "l"(d));
}
__device__ __forceinline__ float2 unpk(ull v) {
    float2 f; asm("mov.b64 {%0, %1}, %2;" : "=f"(f.x), "=f"(f.y) : "l"(v)); return f;
}
__device__ __forceinline__ void ldm_x4(uint32_t* r, uint32_t addr) {
    asm volatile("ldmatrix.sync.aligned.m8n8.x4.shared.b16 {%0,%1,%2,%3}, [%4];"
        : "=r"(r[0]), "=r"(r[1]), "=r"(r[2]), "=r"(r[3]) : "r"(addr));
}
__device__ __forceinline__ void ldm_x4_t(uint32_t* r, uint32_t addr) {
    asm volatile("ldmatrix.sync.aligned.m8n8.x4.trans.shared.b16 {%0,%1,%2,%3}, [%4];"
        : "=r"(r[0]), "=r"(r[1]), "=r"(r[2]), "=r"(r[3]) : "r"(addr));
}
__device__ __forceinline__ void mma16816(float* d, const uint32_t* a, uint32_t b0, uint32_t b1) {
    asm volatile("mma.sync.aligned.m16n8k16.row.col.f32.bf16.bf16.f32 "
        "{%0,%1,%2,%3}, {%4,%5,%6,%7}, {%8,%9}, {%0,%1,%2,%3};"
        : "+f"(d[0]), "+f"(d[1]), "+f"(d[2]), "+f"(d[3])
        : "r"(a[0]), "r"(a[1]), "r"(a[2]), "r"(a[3]), "r"(b0), "r"(b1));
}
__device__ __forceinline__ uint32_t pack_half2(float a, float b) {
    __half2 h = __floats2half2_rn(a, b);
    return *(uint32_t*)&h;
}

__global__ void k0_zero() {
    int t = threadIdx.x;
    if (t < COUT) g_sum[t] = 0.f;
    else if (t < 2 * COUT) g_sq[t - COUT] = 0.f;
}

__global__ void __launch_bounds__(256, 2)
k1_fused(const float* __restrict__ x, const float* __restrict__ adj,
         const float* __restrict__ W, const float* __restrict__ bias)
{
    extern __shared__ char sm[];
    const uint32_t smb = smem_u32(sm);
    float* s_adj  = (float*)(sm + OFF_ADJ);
    float* s_sum  = (float*)(sm + OFF_SSUM);
    float* s_sq   = (float*)(sm + OFF_SSQ);
    float* s_bias = (float*)(sm + OFF_BIAS);
    __nv_bfloat16* whi = (__nv_bfloat16*)(sm + OFF_WHI);
    __nv_bfloat16* wlo = (__nv_bfloat16*)(sm + OFF_WLO);
    __nv_bfloat16* bhi = (__nv_bfloat16*)(sm + OFF_BHI);
    __nv_bfloat16* blo = (__nv_bfloat16*)(sm + OFF_BLO);

    const int tid = threadIdx.x;
    const int wid = tid >> 5;
    const int lid = tid & 31;
    const int blk = blockIdx.x;
    const int b   = blk / NTILES;
    const int tt  = blk - b * NTILES;

    // ---- prologue: adj, bias, W->bf16 hi/lo, zero B pad cols + stats ----
    for (int idx = tid; idx < 650; idx += 256) {
        int v = idx / 26, w = idx - v * 26;
        s_adj[idx] = (w < NV) ? adj[v * NV + w] : 0.f;
    }
    if (tid < COUT) { s_bias[tid] = bias[tid]; s_sum[tid] = 0.f; s_sq[tid] = 0.f; }
    // zero pad cols j=125..127 of both B tiles (rows c=0..63)
    if (tid < 128) {
        int c = tid & 63;
        __nv_bfloat16* bt = (tid < 64) ? bhi : blo;
        bt[c * B_STR + 125] = __nv_bfloat16(0.f);
        bt[c * B_STR + 126] = __nv_bfloat16(0.f);
        bt[c * B_STR + 127] = __nv_bfloat16(0.f);
    }
    for (int idx = tid; idx < COUT * CIN; idx += 256) {
        int o = idx >> 6, c = idx & 63;
        float v = W[idx];
        __nv_bfloat16 h = __float2bfloat16_rn(v);
        __nv_bfloat16 l = __float2bfloat16_rn(v - __bfloat162float(h));
        whi[o * A_STR + c] = h;
        wlo[o * A_STR + c] = l;
    }
    __syncthreads();

    // ---- adjacency (fp32/f32x2) from gmem x -> bf16 hi/lo B tiles ----
    const float* xb = x + (size_t)b * CIN * TV + (size_t)tt * NTILE;
    for (int task = tid; task < CIN * TT; task += 256) {
        int c = task / TT, tl = task - c * TT;
        const float* xr_ptr = xb + (size_t)c * TV + tl * NV;
        float xr[NV];
        #pragma unroll
        for (int v = 0; v < NV; ++v) xr[v] = __ldg(xr_ptr + v);
        ull acc[13];
        #pragma unroll
        for (int p = 0; p < 13; ++p) acc[p] = 0ull;
        #pragma unroll
        for (int v = 0; v < NV; ++v) {
            ull xv = dup2(xr[v]);
            const ull* arow = (const ull*)(s_adj + v * 26);
            #pragma unroll
            for (int p = 0; p < 13; ++p) fma2(acc[p], xv, arow[p]);
        }
        __nv_bfloat16* bh = bhi + c * B_STR + tl * NV;
        __nv_bfloat16* bl = blo + c * B_STR + tl * NV;
        #pragma unroll
        for (int p = 0; p < 13; ++p) {
            float2 f = unpk(acc[p]);
            int w = 2 * p;
            {
                __nv_bfloat16 h = __float2bfloat16_rn(f.x);
                bh[w] = h; bl[w] = __float2bfloat16_rn(f.x - __bfloat162float(h));
            }
            if (w + 1 < NV) {
                __nv_bfloat16 h = __float2bfloat16_rn(f.y);
                bh[w + 1] = h; bl[w + 1] = __float2bfloat16_rn(f.y - __bfloat162float(h));
            }
        }
    }
    __syncthreads();

    // ---- HMMA GEMM: D[128o][128j], 3-term bf16 split ----
    const int warpM = wid >> 1;
    const int warpN = wid & 1;
    const int mbase = warpM * 32;
    const int nbase = warpN * 64;
    const int lrow  = lid & 15;
    const int lcol8 = (lid >> 4) * 8;

    float acc[2][8][4];
    #pragma unroll
    for (int mt = 0; mt < 2; ++mt)
        #pragma unroll
        for (int nt = 0; nt < 8; ++nt)
            #pragma unroll
            for (int e = 0; e < 4; ++e) acc[mt][nt][e] = 0.f;

    #pragma unroll
    for (int ks = 0; ks < 4; ++ks) {
        uint32_t ahi[2][4], alo[2][4];
        #pragma unroll
        for (int mt = 0; mt < 2; ++mt) {
            uint32_t arow = mbase + mt * 16 + lrow;
            uint32_t acolb = ks * 16 + lcol8;
            ldm_x4(ahi[mt], smb + OFF_WHI + (arow * A_STR + acolb) * 2);
            ldm_x4(alo[mt], smb + OFF_WLO + (arow * A_STR + acolb) * 2);
        }
        #pragma unroll
        for (int nh = 0; nh < 2; ++nh) {
            uint32_t bhF[2][4], blF[2][4];
            #pragma unroll
            for (int nt2 = 0; nt2 < 2; ++nt2) {
                uint32_t brow = ks * 16 + lrow;
                uint32_t bcol = nbase + nh * 32 + nt2 * 16 + lcol8;
                ldm_x4_t(bhF[nt2], smb + OFF_BHI + (brow * B_STR + bcol) * 2);
                ldm_x4_t(blF[nt2], smb + OFF_BLO + (brow * B_STR + bcol) * 2);
            }
            #pragma unroll
            for (int mt = 0; mt < 2; ++mt)
                #pragma unroll
                for (int nt = 0; nt < 4; ++nt) {
                    float* d = acc[mt][nh * 4 + nt];
                    uint32_t b0h = bhF[nt >> 1][(nt & 1) * 2], b1h = bhF[nt >> 1][(nt & 1) * 2 + 1];
                    uint32_t b0l = blF[nt >> 1][(nt & 1) * 2], b1l = blF[nt >> 1][(nt & 1) * 2 + 1];
                    mma16816(d, ahi[mt], b0h, b1h);
                    mma16816(d, ahi[mt], b0l, b1l);
                    mma16816(d, alo[mt], b0h, b1h);
                }
        }
    }

    // ---- bias + stats (quad shuffles -> smem atomics) ----
    const int qrow = lid >> 2;
    const int qcol = (lid & 3) * 2;
    float rsum[2][2] = {{0.f, 0.f}, {0.f, 0.f}};
    float rsq[2][2]  = {{0.f, 0.f}, {0.f, 0.f}};
    #pragma unroll
    for (int mt = 0; mt < 2; ++mt) {
        int r0 = mbase + mt * 16 + qrow;
        float b0 = s_bias[r0], b1 = s_bias[r0 + 8];
        #pragma unroll
        for (int nt = 0; nt < 8; ++nt) {
            int j0 = nbase + nt * 8 + qcol;
            float* d = acc[mt][nt];
            d[0] += b0; d[1] += b0; d[2] += b1; d[3] += b1;
            if (j0 < NTILE)     { rsum[mt][0] += d[0]; rsq[mt][0] += d[0] * d[0];
                                  rsum[mt][1] += d[2]; rsq[mt][1] += d[2] * d[2]; }
            if (j0 + 1 < NTILE) { rsum[mt][0] += d[1]; rsq[mt][0] += d[1] * d[1];
                                  rsum[mt][1] += d[3]; rsq[mt][1] += d[3] * d[3]; }
        }
    }
    #pragma unroll
    for (int mt = 0; mt < 2; ++mt)
        #pragma unroll
        for (int rr = 0; rr < 2; ++rr) {
            float s = rsum[mt][rr], q = rsq[mt][rr];
            s += __shfl_xor_sync(0xffffffffu, s, 1); q += __shfl_xor_sync(0xffffffffu, q, 1);
            s += __shfl_xor_sync(0xffffffffu, s, 2); q += __shfl_xor_sync(0xffffffffu, q, 2);
            if ((lid & 3) == 0) {
                int o = mbase + mt * 16 + qrow + rr * 8;
                atomicAdd(&s_sum[o], s);
                atomicAdd(&s_sq[o], q);
            }
        }
    __syncthreads();   // stats done; MMA reads of B tiles done -> staging may overwrite

    // ---- fragments -> fp16 staging [o][j] (stride 136 halves), aliased on B tiles ----
    if (tid < COUT) {
        atomicAdd(&g_sum[tid], s_sum[tid]);
        atomicAdd(&g_sq[tid], s_sq[tid]);
    }
    {
        uint32_t* stage = (uint32_t*)(sm + OFF_BHI);   // half2-addressed
        #pragma unroll
        for (int mt = 0; mt < 2; ++mt) {
            int r0 = mbase + mt * 16 + qrow;
            #pragma unroll
            for (int nt = 0; nt < 8; ++nt) {
                float* d = acc[mt][nt];
                int j0 = nbase + nt * 8 + qcol;
                stage[(r0 * B_STR + j0) >> 1]       = pack_half2(d[0], d[1]);
                stage[((r0 + 8) * B_STR + j0) >> 1] = pack_half2(d[2], d[3]);
            }
        }
    }
    __syncthreads();

    // ---- staging -> gmem fp16 scratch (coalesced 128B per thread) ----
    {
        const __half* stage = (const __half*)(sm + OFF_BHI);
        int o  = tid >> 1;
        int hs = tid & 1;                   // half-row select
        const uint4* src = (const uint4*)(stage + o * B_STR + hs * 64);
        uint4* dst = (uint4*)(g_ys + ((size_t)(b * COUT + o) * NTILES + tt) * 128 + hs * 64);
        #pragma unroll
        for (int k = 0; k < 8; ++k) dst[k] = src[k];
    }
}

__global__ void k2_finalize(const float* __restrict__ gamma, const float* __restrict__ beta) {
    int i = threadIdx.x;
    float mean = g_sum[i] * (1.0f / NCNT);
    float var  = g_sq[i]  * (1.0f / NCNT) - mean * mean;
    float sc   = gamma[i] * rsqrtf(var + 1e-5f);
    g_scale[i] = sc;
    g_shift[i] = beta[i] - mean * sc;
}

__global__ void k3_norm(float* __restrict__ out) {
    unsigned int idx = blockIdx.x * 256u + threadIdx.x;
    unsigned int e = idx * 4u;
    if (e >= 61440000u) return;
    unsigned int row = e / TV;          // b*128+o
    int o = row & 127;
    unsigned int g = e - row * TV;
    float sc = g_scale[o], sh = g_shift[o];
    const __half* yrow = g_ys + (size_t)row * (NTILES * 128);
    float4 r;
    {
        unsigned int gg = g;     unsigned int t0 = gg / NTILE;
        r.x = fmaxf(fmaf(__half2float(yrow[t0 * 128 + (gg - t0 * NTILE)]), sc, sh), 0.f);
    }
    {
        unsigned int gg = g + 1; unsigned int t0 = gg / NTILE;
        r.y = fmaxf(fmaf(__half2float(yrow[t0 * 128 + (gg - t0 * NTILE)]), sc, sh), 0.f);
    }
    {
        unsigned int gg = g + 2; unsigned int t0 = gg / NTILE;
        r.z = fmaxf(fmaf(__half2float(yrow[t0 * 128 + (gg - t0 * NTILE)]), sc, sh), 0.f);
    }
    {
        unsigned int gg = g + 3; unsigned int t0 = gg / NTILE;
        r.w = fmaxf(fmaf(__half2float(yrow[t0 * 128 + (gg - t0 * NTILE)]), sc, sh), 0.f);
    }
    *(float4*)(out + e) = r;
}

extern "C" void kernel_launch(void* const* d_in, const int* in_sizes, int n_in,
                              void* d_out, int out_size)
{
    (void)in_sizes; (void)n_in; (void)out_size;
    const float* x     = (const float*)d_in[0];
    const float* adj   = (const float*)d_in[1];
    const float* W     = (const float*)d_in[2];
    const float* bias  = (const float*)d_in[3];
    const float* gamma = (const float*)d_in[4];
    const float* beta  = (const float*)d_in[5];
    float* out = (float*)d_out;

    cudaFuncSetAttribute(k1_fused, cudaFuncAttributeMaxDynamicSharedMemorySize, SMEM_BYTES);

    k0_zero<<<1, 256>>>();
    k1_fused<<<NB * NTILES, 256, SMEM_BYTES>>>(x, adj, W, bias);
    k2_finalize<<<1, 128>>>(gamma, beta);
    k3_norm<<<60000, 256>>>(out);
}